// round 4
// baseline (speedup 1.0000x reference)
#include <cuda_runtime.h>

#define NXX 64
#define DTT 1e-4f

__device__ __forceinline__ float ex2_fast(float x) {
    float e;
    asm("ex2.approx.f32 %0, %1;" : "=f"(e) : "f"(x));
    return e;
}
__device__ __forceinline__ float rcp_fast(float x) {
    float r;
    asm("rcp.approx.f32 %0, %1;" : "=f"(r) : "f"(x));
    return r;
}

// 256 threads: 4 lanes per grid point (p = tid>>2, s = tid&3).
// Lane s owns 8 hidden units (s<2 -> layer1, else layer2; (s&1) picks half).
// 2 warps per SMSP -> latency hiding across the ex2/rcp dependency chains.
// tanh(x) = 1 - 2/(e^{2x}+1), e^{2x}=2^{Kx} with K=2log2(e) folded into weights.
// QUAD reciprocal: z clamped to <= 31 so a=2^z+1 in (1, 2^31+1]; product of 4
// <= ~2^124 (finite) -> one rcp serves 4 units via partial products.
// Head + gamma + DT folded: un = (uc + DT*core) + [gDT*(sum wc + bc) + sum (-2 gDT wc_m)/a_m].
// uc carried in registers (all 4 lanes recompute un after 2 shfl_xor);
// SMEM ping-pong only for neighbor exchange -> one barrier per step.
__global__ __launch_bounds__(256, 1) void scct_kernel(
    const float* __restrict__ u0,  const float* __restrict__ w1,
    const float* __restrict__ b1,  const float* __restrict__ w2,
    const float* __restrict__ b2,  const float* __restrict__ wc,
    const float* __restrict__ bc,  const float* __restrict__ gamma_p,
    const int*   __restrict__ nt_p, float* __restrict__ out)
{
    __shared__ float ub[2][NXX];

    const int tid = threadIdx.x;
    const int p = tid >> 2;   // grid point 0..63
    const int s = tid & 3;    // hidden-unit sub-slot

    const float K = 2.88539008177792681472f;  // 2*log2(e)

    float Wu[8], Wg[8], Wl[8], Bq[8], Cq[8];
    const float* wsel = (s < 2) ? w1 : w2;
    const float* bsel = (s < 2) ? b1 : b2;
    const int jbase = (s & 1) * 8;

    const float gmm = *gamma_p;
    const float gdt = gmm * DTT;

    float csum = 0.0f;
#pragma unroll
    for (int q = 0; q < 8; q++) {
        int j = jbase + q;
        int m = s * 8 + q;
        Wu[q] = wsel[j * 3 + 0] * K;
        Wg[q] = wsel[j * 3 + 1] * K;
        Wl[q] = wsel[j * 3 + 2] * K;
        Bq[q] = bsel[j] * K;
        float c = wc[m];
        Cq[q] = -2.0f * gdt * c;
        csum += c;
    }
    // Stot = gamma*DT*(sum of ALL 32 wc + bc); every lane holds it.
    csum += __shfl_xor_sync(0xffffffffu, csum, 1);
    csum += __shfl_xor_sync(0xffffffffu, csum, 2);
    const float Stot = gdt * (csum + *bc);

    const int Nt = *nt_p;

    if (tid < NXX) ub[0][tid] = u0[tid];
    __syncthreads();

    const float INV2DX = 31.5f;    // 63/2 exact
    const float INVDX2 = 3969.0f;  // 63^2

    const bool interior = (p > 0) && (p < NXX - 1);
    const int pm = (p == 0) ? 0 : p - 1;
    const int pp = (p == NXX - 1) ? NXX - 1 : p + 1;

    float uc = ub[0][p];
    int cur = 0;

    for (int it = 0; it < Nt; ++it) {
        const float um = ub[cur][pm];
        const float up = ub[cur][pp];

        float gx = 0.0f, lx = 0.0f;
        if (interior) {
            gx = (up - um) * INV2DX;
            lx = ((up - 2.0f * uc) + um) * INVDX2;
        }

        // z and a=2^z+1 for this lane's 8 units (clamped high side only).
        float a[8];
#pragma unroll
        for (int q = 0; q < 8; q++) {
            float z = fmaf(Wu[q], uc, fmaf(Wg[q], gx, fmaf(Wl[q], lx, Bq[q])));
            z = fminf(z, 31.0f);
            a[q] = ex2_fast(z) + 1.0f;
        }

        // Two quad-reciprocal groups -> two MUFU rcp total.
        float P0, P1;
        {
            float b01 = a[0] * a[1], b23 = a[2] * a[3];
            float r   = rcp_fast(b01 * b23);        // <= 2^124: finite
            float r01 = r * b23,  r23 = r * b01;
            float acc0 = Cq[0] * (r01 * a[1]);
            acc0 = fmaf(Cq[1], r01 * a[0], acc0);
            acc0 = fmaf(Cq[2], r23 * a[3], acc0);
            acc0 = fmaf(Cq[3], r23 * a[2], acc0);
            P0 = acc0;
        }
        {
            float b01 = a[4] * a[5], b23 = a[6] * a[7];
            float r   = rcp_fast(b01 * b23);
            float r01 = r * b23,  r23 = r * b01;
            float acc1 = Cq[4] * (r01 * a[5]);
            acc1 = fmaf(Cq[5], r01 * a[4], acc1);
            acc1 = fmaf(Cq[6], r23 * a[7], acc1);
            acc1 = fmaf(Cq[7], r23 * a[6], acc1);
            P1 = acc1;
        }

        float P = P0 + P1;
        P += __shfl_xor_sync(0xffffffffu, P, 1);
        P += __shfl_xor_sync(0xffffffffu, P, 2);   // full gDT * head sum (minus Stot)

        // base computed in parallel with the shfl chain
        const float u3   = uc * uc * uc;
        const float core = fmaf(0.8f, lx, fmaf(0.5f, uc, -u3));
        const float base = fmaf(DTT, core, uc) + Stot;

        float un = base + P;
        un = interior ? un : 0.0f;

        if (s == 0) ub[cur ^ 1][p] = un;
        __syncthreads();
        uc = un;
        cur ^= 1;
    }

    // ---- epilogue: u, phi2, entropy of 64-bin histogram of |u|/max ----
    if (tid < NXX) out[tid] = ub[cur][tid];

    if (tid == 0) {
        const float* uf = ub[cur];
        float s2 = 0.0f, vmax = 0.0f;
        for (int i = 0; i < NXX; i++) {
            float u = uf[i];
            s2 += u * u;
            vmax = fmaxf(vmax, fabsf(u));
        }
        float phi2 = s2 * (1.0f / 64.0f);

        int hist[64];
#pragma unroll
        for (int i = 0; i < 64; i++) hist[i] = 0;
        float denom = fmaxf(vmax, 1e-12f);
        for (int i = 0; i < NXX; i++) {
            float vn = fabsf(uf[i]) / denom;   // IEEE div, matches ref
            int b = (int)(vn * 64.0f);
            if (b > 63) b = 63;
            hist[b]++;
        }
        float H = 0.0f;
        for (int i = 0; i < 64; i++) {
            if (hist[i] > 0) {
                float pb = (float)hist[i] * (1.0f / 64.0f);
                H -= pb * logf(pb);
            }
        }
        if (vmax < 1e-12f) H = 0.0f;
        out[64] = phi2;
        out[65] = H;
    }
}

extern "C" void kernel_launch(void* const* d_in, const int* in_sizes, int n_in,
                              void* d_out, int out_size) {
    (void)in_sizes; (void)n_in; (void)out_size;
    scct_kernel<<<1, 256>>>(
        (const float*)d_in[0],  // u0
        (const float*)d_in[1],  // w1
        (const float*)d_in[2],  // b1
        (const float*)d_in[3],  // w2
        (const float*)d_in[4],  // b2
        (const float*)d_in[5],  // wc
        (const float*)d_in[6],  // bc
        (const float*)d_in[7],  // gamma
        (const int*)  d_in[8],  // Nt
        (float*)d_out);
}

// round 5
// speedup vs baseline: 1.4990x; 1.4990x over previous
#include <cuda_runtime.h>

#define NXX 64
#define DTT 1e-4f

__device__ __forceinline__ float tanh_approx(float x) {
    float t;
    asm("tanh.approx.f32 %0, %1;" : "=f"(t) : "f"(x));
    return t;
}

// 128 threads: 2 lanes per grid point (p = tid>>1, s = tid&1).
// Lane s owns one full 16-unit layer (s=0 -> layer1, s=1 -> layer2).
// tanh via single-instruction MUFU tanh.approx.f32 (abs err ~6e-4; test
// tolerance is 1e-3 relative and drift analysis gives ~1e-4 final error).
// Head + gamma + DT folded into weights: Cq = gamma*DT*wc, so
//   un = uc + DT*core + gamma*DT*bc + sum Cq_m * tanh(z_m).
// uc carried in registers (both lanes recompute un after one shfl_xor);
// SMEM ping-pong only for neighbor exchange -> one barrier per step.
__global__ __launch_bounds__(128, 1) void scct_kernel(
    const float* __restrict__ u0,  const float* __restrict__ w1,
    const float* __restrict__ b1,  const float* __restrict__ w2,
    const float* __restrict__ b2,  const float* __restrict__ wc,
    const float* __restrict__ bc,  const float* __restrict__ gamma_p,
    const int*   __restrict__ nt_p, float* __restrict__ out)
{
    __shared__ float ub[2][NXX];

    const int tid = threadIdx.x;
    const int p = tid >> 1;   // grid point 0..63
    const int s = tid & 1;    // layer select

    float Wu[16], Wg[16], Wl[16], Bq[16], Cq[16];
    const float* wsel = s ? w2 : w1;
    const float* bsel = s ? b2 : b1;

    const float gmm = *gamma_p;
    const float gdt = gmm * DTT;

#pragma unroll
    for (int q = 0; q < 16; q++) {
        Wu[q] = wsel[q * 3 + 0];
        Wg[q] = wsel[q * 3 + 1];
        Wl[q] = wsel[q * 3 + 2];
        Bq[q] = bsel[q];
        Cq[q] = gdt * wc[s * 16 + q];
    }
    const float Kc = gdt * (*bc);   // constant head term (applied once per step)
    const int Nt = *nt_p;

    if (tid < NXX) ub[0][tid] = u0[tid];
    __syncthreads();

    const float INV2DX = 31.5f;    // 63/2 exact
    const float INVDX2 = 3969.0f;  // 63^2

    const bool interior = (p > 0) && (p < NXX - 1);
    const int pm = (p == 0) ? 0 : p - 1;
    const int pp = (p == NXX - 1) ? NXX - 1 : p + 1;

    float uc = ub[0][p];
    int cur = 0;

    for (int it = 0; it < Nt; ++it) {
        const float um = ub[cur][pm];
        const float up = ub[cur][pp];

        float gx = 0.0f, lx = 0.0f;
        if (interior) {
            gx = (up - um) * INV2DX;
            lx = ((up - 2.0f * uc) + um) * INVDX2;
        }

        // 16 units, 4 independent accumulation chains for ILP.
        float A0 = 0.0f, A1 = 0.0f, A2 = 0.0f, A3 = 0.0f;
#pragma unroll
        for (int j = 0; j < 4; j++) {
            const int q0 = 4 * j, q1 = 4 * j + 1, q2 = 4 * j + 2, q3 = 4 * j + 3;
            float z0 = fmaf(Wu[q0], uc, fmaf(Wg[q0], gx, fmaf(Wl[q0], lx, Bq[q0])));
            float z1 = fmaf(Wu[q1], uc, fmaf(Wg[q1], gx, fmaf(Wl[q1], lx, Bq[q1])));
            float z2 = fmaf(Wu[q2], uc, fmaf(Wg[q2], gx, fmaf(Wl[q2], lx, Bq[q2])));
            float z3 = fmaf(Wu[q3], uc, fmaf(Wg[q3], gx, fmaf(Wl[q3], lx, Bq[q3])));
            A0 = fmaf(Cq[q0], tanh_approx(z0), A0);
            A1 = fmaf(Cq[q1], tanh_approx(z1), A1);
            A2 = fmaf(Cq[q2], tanh_approx(z2), A2);
            A3 = fmaf(Cq[q3], tanh_approx(z3), A3);
        }
        float P = (A0 + A1) + (A2 + A3);
        P += __shfl_xor_sync(0xffffffffu, P, 1);   // both lanes get full head sum

        // base computed in parallel with the shfl
        const float u3   = uc * uc * uc;
        const float core = fmaf(0.8f, lx, fmaf(0.5f, uc, -u3));
        const float base = fmaf(DTT, core, uc) + Kc;

        float un = base + P;
        un = interior ? un : 0.0f;

        if (s == 0) ub[cur ^ 1][p] = un;
        __syncthreads();
        uc = un;
        cur ^= 1;
    }

    // ---- epilogue: u, phi2, entropy of 64-bin histogram of |u|/max ----
    if (tid < NXX) out[tid] = ub[cur][tid];

    if (tid == 0) {
        const float* uf = ub[cur];
        float s2 = 0.0f, vmax = 0.0f;
        for (int i = 0; i < NXX; i++) {
            float u = uf[i];
            s2 += u * u;
            vmax = fmaxf(vmax, fabsf(u));
        }
        float phi2 = s2 * (1.0f / 64.0f);

        int hist[64];
#pragma unroll
        for (int i = 0; i < 64; i++) hist[i] = 0;
        float denom = fmaxf(vmax, 1e-12f);
        for (int i = 0; i < NXX; i++) {
            float vn = fabsf(uf[i]) / denom;   // IEEE div, matches ref
            int b = (int)(vn * 64.0f);
            if (b > 63) b = 63;
            hist[b]++;
        }
        float H = 0.0f;
        for (int i = 0; i < 64; i++) {
            if (hist[i] > 0) {
                float pb = (float)hist[i] * (1.0f / 64.0f);
                H -= pb * logf(pb);
            }
        }
        if (vmax < 1e-12f) H = 0.0f;
        out[64] = phi2;
        out[65] = H;
    }
}

extern "C" void kernel_launch(void* const* d_in, const int* in_sizes, int n_in,
                              void* d_out, int out_size) {
    (void)in_sizes; (void)n_in; (void)out_size;
    scct_kernel<<<1, 128>>>(
        (const float*)d_in[0],  // u0
        (const float*)d_in[1],  // w1
        (const float*)d_in[2],  // b1
        (const float*)d_in[3],  // w2
        (const float*)d_in[4],  // b2
        (const float*)d_in[5],  // wc
        (const float*)d_in[6],  // bc
        (const float*)d_in[7],  // gamma
        (const int*)  d_in[8],  // Nt
        (float*)d_out);
}

// round 6
// speedup vs baseline: 1.8536x; 1.2366x over previous
#include <cuda_runtime.h>
#include <cstdint>

#define NXX 64
#define DTT 1e-4f

__device__ __forceinline__ float tanh_approx(float x) {
    float t;
    asm("tanh.approx.f32 %0, %1;" : "=f"(t) : "f"(x));
    return t;
}
__device__ __forceinline__ uint64_t pack2(float lo, float hi) {
    uint64_t r;
    asm("mov.b64 %0, {%1, %2};" : "=l"(r) : "f"(lo), "f"(hi));
    return r;
}
__device__ __forceinline__ void unpack2(uint64_t v, float& lo, float& hi) {
    asm("mov.b64 {%0, %1}, %2;" : "=f"(lo), "=f"(hi) : "l"(v));
}
__device__ __forceinline__ uint64_t fma2(uint64_t a, uint64_t b, uint64_t c) {
    uint64_t d;
    asm("fma.rn.f32x2 %0, %1, %2, %3;" : "=l"(d) : "l"(a), "l"(b), "l"(c));
    return d;
}
__device__ __forceinline__ uint64_t add2(uint64_t a, uint64_t b) {
    uint64_t d;
    asm("add.rn.f32x2 %0, %1, %2;" : "=l"(d) : "l"(a), "l"(b));
    return d;
}

// 128 threads: 2 lanes per grid point (p = tid>>1, s = tid&1).
// Lane s owns one full 16-unit layer, processed as 8 f32x2 PAIRS (FFMA2
// halves the FMA-pipe + issue load; MUFU tanh.approx is then the floor).
// Stencil folded into weights: z = Wp*up + Wm*um + zb, where
//   Wp = 31.5*Wg + 3969*Wl, Wm = -31.5*Wg + 3969*Wl, Wuc = Wu - 7938*Wl
// (folds in f64 at init; boundary lanes get Wp=Wm=0, Wuc=Wu).
// zb = Wuc*u + B and cb = 0.5u - u^3 are computed in the BARRIER SHADOW
// (from un, before __syncthreads), so the post-barrier chain is
// LDS -> 2 packed fmas -> tanh -> acc -> shfl -> store.
// Head fully folded: Cq = gamma*DT*wc; un = uc + DT*core + gamma*DT*bc + P.
__global__ __launch_bounds__(128, 1) void scct_kernel(
    const float* __restrict__ u0,  const float* __restrict__ w1,
    const float* __restrict__ b1,  const float* __restrict__ w2,
    const float* __restrict__ b2,  const float* __restrict__ wc,
    const float* __restrict__ bc,  const float* __restrict__ gamma_p,
    const int*   __restrict__ nt_p, float* __restrict__ out)
{
    __shared__ float ub[2][NXX];

    const int tid = threadIdx.x;
    const int p = tid >> 1;   // grid point 0..63
    const int s = tid & 1;    // layer select

    const float* wsel = s ? w2 : w1;
    const float* bsel = s ? b2 : b1;

    const float gmm = *gamma_p;
    const float gdt = gmm * DTT;
    const bool interior = (p > 0) && (p < NXX - 1);

    uint64_t Wp2[8], Wm2[8], Wuc2[8], Bq2[8], Cq2[8];
#pragma unroll
    for (int j = 0; j < 8; j++) {
        float pl[2], ml[2], ul[2], bl[2], cl[2];
#pragma unroll
        for (int h = 0; h < 2; h++) {
            int q = 2 * j + h;
            double Wu = (double)wsel[q * 3 + 0];
            double Wg = (double)wsel[q * 3 + 1];
            double Wl = (double)wsel[q * 3 + 2];
            if (interior) {
                pl[h] = (float)( 31.5 * Wg + 3969.0 * Wl);
                ml[h] = (float)(-31.5 * Wg + 3969.0 * Wl);
                ul[h] = (float)(Wu - 7938.0 * Wl);
            } else {
                pl[h] = 0.0f;
                ml[h] = 0.0f;
                ul[h] = (float)Wu;
            }
            bl[h] = bsel[q];
            cl[h] = gdt * wc[s * 16 + q];
        }
        Wp2[j]  = pack2(pl[0], pl[1]);
        Wm2[j]  = pack2(ml[0], ml[1]);
        Wuc2[j] = pack2(ul[0], ul[1]);
        Bq2[j]  = pack2(bl[0], bl[1]);
        Cq2[j]  = pack2(cl[0], cl[1]);
    }
    const float Kc = gdt * (*bc);
    const int Nt = *nt_p;

    if (tid < NXX) ub[0][tid] = u0[tid];
    __syncthreads();

    const float INVDX2 = 3969.0f;  // 63^2

    const int pm = (p == 0) ? 0 : p - 1;
    const int pp = (p == NXX - 1) ? NXX - 1 : p + 1;

    float uc = ub[0][p];
    int cur = 0;

    // Initial barrier-shadow values from u0.
    uint64_t zb2[8];
    {
        uint64_t uc2 = pack2(uc, uc);
#pragma unroll
        for (int j = 0; j < 8; j++) zb2[j] = fma2(Wuc2[j], uc2, Bq2[j]);
    }
    float cb = fmaf(0.5f, uc, -(uc * uc * uc));   // 0.5u - u^3

    for (int it = 0; it < Nt; ++it) {
        const float um = ub[cur][pm];
        const float up = ub[cur][pp];
        const uint64_t um2 = pack2(um, um);
        const uint64_t up2 = pack2(up, up);

        uint64_t A0 = 0ull, A1 = 0ull;
#pragma unroll
        for (int j = 0; j < 8; j++) {
            uint64_t z2 = fma2(Wp2[j], up2, fma2(Wm2[j], um2, zb2[j]));
            float zl, zh;
            unpack2(z2, zl, zh);
            uint64_t t2 = pack2(tanh_approx(zl), tanh_approx(zh));
            if (j & 1) A1 = fma2(Cq2[j], t2, A1);
            else       A0 = fma2(Cq2[j], t2, A0);
        }
        float al, ah;
        unpack2(add2(A0, A1), al, ah);
        float P = al + ah;
        P += __shfl_xor_sync(0xffffffffu, P, 1);   // both lanes: full head sum

        // core/base overlap the shfl
        const float lx   = ((up - 2.0f * uc) + um) * INVDX2;
        const float core = fmaf(0.8f, lx, cb);
        const float base = fmaf(DTT, core, uc) + Kc;

        float un = base + P;
        un = interior ? un : 0.0f;

        if (s == 0) ub[cur ^ 1][p] = un;

        // ---- barrier shadow: next step's zb and cb from un ----
        {
            uint64_t un2 = pack2(un, un);
#pragma unroll
            for (int j = 0; j < 8; j++) zb2[j] = fma2(Wuc2[j], un2, Bq2[j]);
        }
        cb = fmaf(0.5f, un, -(un * un * un));

        __syncthreads();
        uc = un;
        cur ^= 1;
    }

    // ---- epilogue: u, phi2, entropy of 64-bin histogram of |u|/max ----
    if (tid < NXX) out[tid] = ub[cur][tid];

    if (tid == 0) {
        const float* uf = ub[cur];
        float s2 = 0.0f, vmax = 0.0f;
        for (int i = 0; i < NXX; i++) {
            float u = uf[i];
            s2 += u * u;
            vmax = fmaxf(vmax, fabsf(u));
        }
        float phi2 = s2 * (1.0f / 64.0f);

        int hist[64];
#pragma unroll
        for (int i = 0; i < 64; i++) hist[i] = 0;
        float denom = fmaxf(vmax, 1e-12f);
        for (int i = 0; i < NXX; i++) {
            float vn = fabsf(uf[i]) / denom;   // IEEE div, matches ref
            int b = (int)(vn * 64.0f);
            if (b > 63) b = 63;
            hist[b]++;
        }
        float H = 0.0f;
        for (int i = 0; i < 64; i++) {
            if (hist[i] > 0) {
                float pb = (float)hist[i] * (1.0f / 64.0f);
                H -= pb * logf(pb);
            }
        }
        if (vmax < 1e-12f) H = 0.0f;
        out[64] = phi2;
        out[65] = H;
    }
}

extern "C" void kernel_launch(void* const* d_in, const int* in_sizes, int n_in,
                              void* d_out, int out_size) {
    (void)in_sizes; (void)n_in; (void)out_size;
    scct_kernel<<<1, 128>>>(
        (const float*)d_in[0],  // u0
        (const float*)d_in[1],  // w1
        (const float*)d_in[2],  // b1
        (const float*)d_in[3],  // w2
        (const float*)d_in[4],  // b2
        (const float*)d_in[5],  // wc
        (const float*)d_in[6],  // bc
        (const float*)d_in[7],  // gamma
        (const int*)  d_in[8],  // Nt
        (float*)d_out);
}